// round 12
// baseline (speedup 1.0000x reference)
#include <cuda_runtime.h>
#include <cstdint>

#define N_PTS   400000
#define NXY     468
#define CANVAS  (468 * 468)          // 219024
#define VXY     0.32f
#define VZf     6.0f
#define PCMINX  (-74.88f)
#define PCMINY  (-74.88f)
#define PCMINZ  (-2.0f)

// -------- scratch (static device globals; no allocations allowed) ----------
__device__ int   g_flat[N_PTS];
__device__ int   g_cnt[CANVAS];
__device__ float g_vsum[CANVAS * 3];
__device__ float g_v1[CANVAS * 64];             // 56 MB
__device__ float g_M[CANVAS * 64];              // 56 MB  pre-relu segment max

#define NEG_INF_BITS 0xff800000u

// ---------------------------------------------------------------------------
// K0: zero cnt / vsum / v1 ; fill M with -inf. (out written densely by k_vox)
// ---------------------------------------------------------------------------
__global__ void k_init() {
    int idx = blockIdx.x * blockDim.x + threadIdx.x;
    int stride = gridDim.x * blockDim.x;
    const int n4 = (CANVAS * 64) / 4;
    float4 z = make_float4(0.f, 0.f, 0.f, 0.f);
    float ninf = __uint_as_float(NEG_INF_BITS);
    float4 nf = make_float4(ninf, ninf, ninf, ninf);
    float4* v4 = (float4*)g_v1;
    float4* m4 = (float4*)g_M;
    for (int i = idx; i < n4; i += stride) {
        v4[i] = z;
        m4[i] = nf;
    }
    for (int i = idx; i < CANVAS; i += stride) {
        g_cnt[i] = 0;
        g_vsum[3 * i + 0] = 0.f;
        g_vsum[3 * i + 1] = 0.f;
        g_vsum[3 * i + 2] = 0.f;
    }
}

// ---------------------------------------------------------------------------
// K1: per-point voxel index + count / xyz-sum scatter
// ---------------------------------------------------------------------------
__device__ __forceinline__ int voxel_coord(float v, float vmin, float vox, int nmax) {
    int c = (int)floorf(__fdiv_rn(v - vmin, vox));
    return min(max(c, 0), nmax - 1);
}

__global__ void k_scatter(const float* __restrict__ pts) {
    int i = blockIdx.x * blockDim.x + threadIdx.x;
    if (i >= N_PTS) return;
    float x = pts[i * 5 + 0];
    float y = pts[i * 5 + 1];
    float z = pts[i * 5 + 2];
    int cx = voxel_coord(x, PCMINX, VXY, NXY);
    int cy = voxel_coord(y, PCMINY, VXY, NXY);
    int flat = cy * NXY + cx;          // NZ==1 -> cz always 0
    g_flat[i] = flat;
    atomicAdd(&g_cnt[flat], 1);
    atomicAdd(&g_vsum[3 * flat + 0], x);
    atomicAdd(&g_vsum[3 * flat + 1], y);
    atomicAdd(&g_vsum[3 * flat + 2], z);
}

// ---------------------------------------------------------------------------
// float atomic max with negatives: sign>=0 -> int max; sign<0 -> uint min.
// Init -inf. Exact, order-independent.
// ---------------------------------------------------------------------------
__device__ __forceinline__ void atomicMaxFloat(float* addr, float v) {
    int b = __float_as_int(v);
    if (b >= 0) atomicMax((int*)addr, b);
    else        atomicMin((unsigned int*)addr, (unsigned int)b);
}

#define SA_LD 66    // A row stride (words): 4*66 = 264 = 8 mod 32 -> 4 rows
                    // of a LDS.32 broadcast group hit 4 distinct banks.

// ---------------------------------------------------------------------------
// K2 (fused): per 64-point tile:
//   phase 0: threads 0..63 build f[11] per point ONCE into sF (dedup'd loads)
//   phase 1: pf1 = relu(f @ W1) into sA (4 thr/pt x 16 ch) + atomicMax to v1
//   phase 2: s = pf1 @ W2[:64]  (4x4 micro-tile, K=64)
//   epilogue: pre-relu scatter atomicMaxFloat into M[flat]
// ---------------------------------------------------------------------------
__global__ __launch_bounds__(256)
void k_fused(const float* __restrict__ pts, const float* __restrict__ W1,
             const float* __restrict__ W2) {
    __shared__ __align__(16) float sW1[11 * 64];
    __shared__ __align__(16) float sW[64 * 64];
    __shared__ __align__(16) float sA[64 * SA_LD];
    __shared__ float sF[64 * 12];
    __shared__ int   sFlat[64];

    int tid = threadIdx.x;
    int p0 = blockIdx.x * 64;          // 6250 * 64 = 400000 exactly
    int tx = tid & 15;
    int ty = tid >> 4;

    for (int i = tid; i < 11 * 64; i += 256) sW1[i] = W1[i];
    for (int i = tid; i < 4096; i += 256) sW[i] = W2[i];   // W2 rows 0..63

    // ---- phase 0: one thread per point builds the 11-feature vector
    if (tid < 64) {
        int gp = p0 + tid;
        float x  = pts[gp * 5 + 0];
        float y  = pts[gp * 5 + 1];
        float z  = pts[gp * 5 + 2];
        float p3 = pts[gp * 5 + 3];
        float p4 = pts[gp * 5 + 4];

        int flat = g_flat[gp];
        sFlat[tid] = flat;
        float inv = 1.0f / fmaxf((float)g_cnt[flat], 1.0f);
        float mx = g_vsum[3 * flat + 0] * inv;
        float my = g_vsum[3 * flat + 1] * inv;
        float mz = g_vsum[3 * flat + 2] * inv;

        int cxv = flat % NXY;
        int cyv = flat / NXY;

        float* f = sF + tid * 12;
        f[0] = x;  f[1] = y;  f[2] = z;  f[3] = p3;  f[4] = p4;
        f[5] = x - mx;  f[6] = y - my;  f[7] = z - mz;
        f[8]  = x - ((float)cxv * VXY + (VXY * 0.5f + PCMINX));
        f[9]  = y - ((float)cyv * VXY + (VXY * 0.5f + PCMINY));
        f[10] = z - (VZf * 0.5f + PCMINZ);
    }
    __syncthreads();

    // ---- phase 1: pf1 channels; thread = (pt, cg): channels cg*16..+15
    {
        int pt = tid >> 2;
        int cg = tid & 3;
        int flat = sFlat[pt];

        float f[11];
        #pragma unroll
        for (int k = 0; k < 11; k++) f[k] = sF[pt * 12 + k];

        const float4* w4 = (const float4*)sW1;   // [11][16] float4
        #pragma unroll
        for (int c4 = 0; c4 < 4; c4++) {
            int ch = cg * 16 + c4 * 4;
            float a0 = 0.f, a1 = 0.f, a2 = 0.f, a3 = 0.f;
            #pragma unroll
            for (int k = 0; k < 11; k++) {
                float4 w = w4[k * 16 + (ch >> 2)];
                a0 = fmaf(f[k], w.x, a0);
                a1 = fmaf(f[k], w.y, a1);
                a2 = fmaf(f[k], w.z, a2);
                a3 = fmaf(f[k], w.w, a3);
            }
            a0 = fmaxf(a0, 0.f); a1 = fmaxf(a1, 0.f);
            a2 = fmaxf(a2, 0.f); a3 = fmaxf(a3, 0.f);

            float* d = sA + pt * SA_LD + ch;
            d[0] = a0; d[1] = a1; d[2] = a2; d[3] = a3;

            int* vb = (int*)&g_v1[(size_t)flat * 64 + ch];
            if (a0 > 0.f) atomicMax(vb + 0, __float_as_int(a0));
            if (a1 > 0.f) atomicMax(vb + 1, __float_as_int(a1));
            if (a2 > 0.f) atomicMax(vb + 2, __float_as_int(a2));
            if (a3 > 0.f) atomicMax(vb + 3, __float_as_int(a3));
        }
    }
    __syncthreads();

    // ---- phase 2: GEMM (4x4 micro-tile, K=64)
    float acc[4][4];
    #pragma unroll
    for (int r = 0; r < 4; r++)
        #pragma unroll
        for (int c = 0; c < 4; c++) acc[r][c] = 0.f;

    #pragma unroll 16
    for (int k = 0; k < 64; k++) {
        float4 b = *(const float4*)&sW[k * 64 + tx * 4];
        float a0 = sA[(ty * 4 + 0) * SA_LD + k];
        float a1 = sA[(ty * 4 + 1) * SA_LD + k];
        float a2 = sA[(ty * 4 + 2) * SA_LD + k];
        float a3 = sA[(ty * 4 + 3) * SA_LD + k];
        acc[0][0] = fmaf(a0, b.x, acc[0][0]); acc[0][1] = fmaf(a0, b.y, acc[0][1]);
        acc[0][2] = fmaf(a0, b.z, acc[0][2]); acc[0][3] = fmaf(a0, b.w, acc[0][3]);
        acc[1][0] = fmaf(a1, b.x, acc[1][0]); acc[1][1] = fmaf(a1, b.y, acc[1][1]);
        acc[1][2] = fmaf(a1, b.z, acc[1][2]); acc[1][3] = fmaf(a1, b.w, acc[1][3]);
        acc[2][0] = fmaf(a2, b.x, acc[2][0]); acc[2][1] = fmaf(a2, b.y, acc[2][1]);
        acc[2][2] = fmaf(a2, b.z, acc[2][2]); acc[2][3] = fmaf(a2, b.w, acc[2][3]);
        acc[3][0] = fmaf(a3, b.x, acc[3][0]); acc[3][1] = fmaf(a3, b.y, acc[3][1]);
        acc[3][2] = fmaf(a3, b.z, acc[3][2]); acc[3][3] = fmaf(a3, b.w, acc[3][3]);
    }

    // ---- epilogue: pre-relu scatter max into M
    #pragma unroll
    for (int r = 0; r < 4; r++) {
        int fl = sFlat[ty * 4 + r];
        float* o = g_M + (size_t)fl * 64 + tx * 4;
        #pragma unroll
        for (int c = 0; c < 4; c++) atomicMaxFloat(o + c, acc[r][c]);
    }
}

// ---------------------------------------------------------------------------
// K3: out[v] = relu(M[v] + v1[v] @ W2[64:]) for every voxel (dense write).
// 128-voxel tile, 4x8 micro-tile, dynamic smem.
// Empty voxels: M=-inf, v1=0 -> 0.
// ---------------------------------------------------------------------------
#define VW_WORDS (64 * 64)
#define VA_WORDS (128 * SA_LD)
#define SMEM_VOX ((VW_WORDS + VA_WORDS) * 4)     // 50176 bytes

__global__ __launch_bounds__(256)
void k_vox(const float* __restrict__ W2, float* __restrict__ out) {
    extern __shared__ float smem[];
    float* sW = smem;                  // [64][64]
    float* sA = smem + VW_WORDS;       // [128][SA_LD]

    int tid = threadIdx.x;
    int v0 = blockIdx.x * 128;
    int ty = tid >> 3;                 // 0..31 -> voxels ty*4..+3
    int tx = tid & 7;                  // 0..7  -> cols tx*8..+7

    for (int i = tid; i < 4096; i += 256) sW[i] = W2[4096 + i];  // rows 64..127

    // stage A: 128 voxel rows x 16 float4 = 2048 loads
    for (int i = tid; i < 2048; i += 256) {
        int r = i >> 4, q = i & 15;
        int v = min(v0 + r, CANVAS - 1);
        float4 vv = ((const float4*)(g_v1 + (size_t)v * 64))[q];
        float* d = sA + r * SA_LD + q * 4;       // r*66+q*4 even -> float2 ok
        *(float2*)(d + 0) = make_float2(vv.x, vv.y);
        *(float2*)(d + 2) = make_float2(vv.z, vv.w);
    }
    __syncthreads();

    float acc[4][8];
    #pragma unroll
    for (int r = 0; r < 4; r++)
        #pragma unroll
        for (int c = 0; c < 8; c++) acc[r][c] = 0.f;

    #pragma unroll 8
    for (int k = 0; k < 64; k++) {
        const float* bp = sW + k * 64 + tx * 8;
        float4 b0 = *(const float4*)(bp + 0);
        float4 b1 = *(const float4*)(bp + 4);
        float a0 = sA[(ty * 4 + 0) * SA_LD + k];
        float a1 = sA[(ty * 4 + 1) * SA_LD + k];
        float a2 = sA[(ty * 4 + 2) * SA_LD + k];
        float a3 = sA[(ty * 4 + 3) * SA_LD + k];
        acc[0][0] = fmaf(a0, b0.x, acc[0][0]); acc[0][1] = fmaf(a0, b0.y, acc[0][1]);
        acc[0][2] = fmaf(a0, b0.z, acc[0][2]); acc[0][3] = fmaf(a0, b0.w, acc[0][3]);
        acc[0][4] = fmaf(a0, b1.x, acc[0][4]); acc[0][5] = fmaf(a0, b1.y, acc[0][5]);
        acc[0][6] = fmaf(a0, b1.z, acc[0][6]); acc[0][7] = fmaf(a0, b1.w, acc[0][7]);
        acc[1][0] = fmaf(a1, b0.x, acc[1][0]); acc[1][1] = fmaf(a1, b0.y, acc[1][1]);
        acc[1][2] = fmaf(a1, b0.z, acc[1][2]); acc[1][3] = fmaf(a1, b0.w, acc[1][3]);
        acc[1][4] = fmaf(a1, b1.x, acc[1][4]); acc[1][5] = fmaf(a1, b1.y, acc[1][5]);
        acc[1][6] = fmaf(a1, b1.z, acc[1][6]); acc[1][7] = fmaf(a1, b1.w, acc[1][7]);
        acc[2][0] = fmaf(a2, b0.x, acc[2][0]); acc[2][1] = fmaf(a2, b0.y, acc[2][1]);
        acc[2][2] = fmaf(a2, b0.z, acc[2][2]); acc[2][3] = fmaf(a2, b0.w, acc[2][3]);
        acc[2][4] = fmaf(a2, b1.x, acc[2][4]); acc[2][5] = fmaf(a2, b1.y, acc[2][5]);
        acc[2][6] = fmaf(a2, b1.z, acc[2][6]); acc[2][7] = fmaf(a2, b1.w, acc[2][7]);
        acc[3][0] = fmaf(a3, b0.x, acc[3][0]); acc[3][1] = fmaf(a3, b0.y, acc[3][1]);
        acc[3][2] = fmaf(a3, b0.z, acc[3][2]); acc[3][3] = fmaf(a3, b0.w, acc[3][3]);
        acc[3][4] = fmaf(a3, b1.x, acc[3][4]); acc[3][5] = fmaf(a3, b1.y, acc[3][5]);
        acc[3][6] = fmaf(a3, b1.z, acc[3][6]); acc[3][7] = fmaf(a3, b1.w, acc[3][7]);
    }

    // epilogue: out = relu(acc + M), dense coalesced
    #pragma unroll
    for (int r = 0; r < 4; r++) {
        int v = v0 + ty * 4 + r;
        if (v >= CANVAS) continue;
        const float4* m4 = (const float4*)(g_M + (size_t)v * 64 + tx * 8);
        float4 mlo = m4[0], mhi = m4[1];
        float4 o0, o1;
        o0.x = fmaxf(acc[r][0] + mlo.x, 0.f);
        o0.y = fmaxf(acc[r][1] + mlo.y, 0.f);
        o0.z = fmaxf(acc[r][2] + mlo.z, 0.f);
        o0.w = fmaxf(acc[r][3] + mlo.w, 0.f);
        o1.x = fmaxf(acc[r][4] + mhi.x, 0.f);
        o1.y = fmaxf(acc[r][5] + mhi.y, 0.f);
        o1.z = fmaxf(acc[r][6] + mhi.z, 0.f);
        o1.w = fmaxf(acc[r][7] + mhi.w, 0.f);
        float4* op = (float4*)(out + (size_t)v * 64 + tx * 8);
        op[0] = o0;
        op[1] = o1;
    }
}

// ---------------------------------------------------------------------------
extern "C" void kernel_launch(void* const* d_in, const int* in_sizes, int n_in,
                              void* d_out, int out_size) {
    const float* points = (const float*)d_in[0];  // [400000, 5]
    const float* W1     = (const float*)d_in[1];  // [11, 64]
    const float* W2     = (const float*)d_in[2];  // [128, 64]
    float* out = (float*)d_out;                   // [219024, 64]

    cudaFuncSetAttribute(k_vox, cudaFuncAttributeMaxDynamicSharedMemorySize,
                         SMEM_VOX);

    k_init<<<8192, 256>>>();
    k_scatter<<<(N_PTS + 255) / 256, 256>>>(points);
    k_fused<<<N_PTS / 64, 256>>>(points, W1, W2);
    k_vox<<<(CANVAS + 127) / 128, 256, SMEM_VOX>>>(W2, out);
}

// round 13
// speedup vs baseline: 1.0718x; 1.0718x over previous
#include <cuda_runtime.h>
#include <cstdint>

#define N_PTS   400000
#define NXY     468
#define CANVAS  (468 * 468)          // 219024
#define VXY     0.32f
#define VZf     6.0f
#define PCMINX  (-74.88f)
#define PCMINY  (-74.88f)
#define PCMINZ  (-2.0f)

// -------- scratch (static device globals; no allocations allowed) ----------
__device__ int   g_flat[N_PTS];
__device__ int   g_cnt[CANVAS];
__device__ float g_vsum[CANVAS * 3];
__device__ float g_v1[CANVAS * 64];             // 56 MB
__device__ float g_M[CANVAS * 64];              // 56 MB  pre-relu segment max

#define NEG_INF_BITS 0xff800000u

// ---------------------------------------------------------------------------
// K0a: zero cnt / vsum (tiny -> scatter can start immediately)
// ---------------------------------------------------------------------------
__global__ void k_init_small() {
    int idx = blockIdx.x * blockDim.x + threadIdx.x;
    int stride = gridDim.x * blockDim.x;
    for (int i = idx; i < CANVAS; i += stride) {
        g_cnt[i] = 0;
        g_vsum[3 * i + 0] = 0.f;
        g_vsum[3 * i + 1] = 0.f;
        g_vsum[3 * i + 2] = 0.f;
    }
}

// ---------------------------------------------------------------------------
// K0b: zero v1, fill M with -inf (112 MB; runs concurrently with scatter)
// ---------------------------------------------------------------------------
__global__ void k_init_big() {
    int idx = blockIdx.x * blockDim.x + threadIdx.x;
    int stride = gridDim.x * blockDim.x;
    const int n4 = (CANVAS * 64) / 4;
    float4 z = make_float4(0.f, 0.f, 0.f, 0.f);
    float ninf = __uint_as_float(NEG_INF_BITS);
    float4 nf = make_float4(ninf, ninf, ninf, ninf);
    float4* v4 = (float4*)g_v1;
    float4* m4 = (float4*)g_M;
    for (int i = idx; i < n4; i += stride) {
        v4[i] = z;
        m4[i] = nf;
    }
}

// ---------------------------------------------------------------------------
// K1: per-point voxel index + count / xyz-sum scatter
// ---------------------------------------------------------------------------
__device__ __forceinline__ int voxel_coord(float v, float vmin, float vox, int nmax) {
    int c = (int)floorf(__fdiv_rn(v - vmin, vox));
    return min(max(c, 0), nmax - 1);
}

__global__ void k_scatter(const float* __restrict__ pts) {
    int i = blockIdx.x * blockDim.x + threadIdx.x;
    if (i >= N_PTS) return;
    float x = pts[i * 5 + 0];
    float y = pts[i * 5 + 1];
    float z = pts[i * 5 + 2];
    int cx = voxel_coord(x, PCMINX, VXY, NXY);
    int cy = voxel_coord(y, PCMINY, VXY, NXY);
    int flat = cy * NXY + cx;          // NZ==1 -> cz always 0
    g_flat[i] = flat;
    atomicAdd(&g_cnt[flat], 1);
    atomicAdd(&g_vsum[3 * flat + 0], x);
    atomicAdd(&g_vsum[3 * flat + 1], y);
    atomicAdd(&g_vsum[3 * flat + 2], z);
}

// ---------------------------------------------------------------------------
// float atomic max with negatives: sign>=0 -> int max; sign<0 -> uint min.
// Init -inf. Exact, order-independent.
// ---------------------------------------------------------------------------
__device__ __forceinline__ void atomicMaxFloat(float* addr, float v) {
    int b = __float_as_int(v);
    if (b >= 0) atomicMax((int*)addr, b);
    else        atomicMin((unsigned int*)addr, (unsigned int)b);
}

#define SA_LD 68

// ---------------------------------------------------------------------------
// K2 (fused, R11-proven): per 64-point tile:
//   stage 1: pf1 = relu(features @ W1) into sA (4 thr/pt x 16 ch) + v1 atomics
//   stage 2: s = pf1 @ W2[:64]  (4x4 micro-tile, K=64)
//   epilogue: pre-relu scatter atomicMaxFloat into M[flat]
// ---------------------------------------------------------------------------
__global__ __launch_bounds__(256)
void k_fused(const float* __restrict__ pts, const float* __restrict__ W1,
             const float* __restrict__ W2) {
    __shared__ __align__(16) float sW1[11 * 64];
    __shared__ __align__(16) float sW[64 * 64];
    __shared__ __align__(16) float sA[64 * SA_LD];

    int tid = threadIdx.x;
    int p0 = blockIdx.x * 64;          // 6250 * 64 = 400000 exactly
    int tx = tid & 15;
    int ty = tid >> 4;

    for (int i = tid; i < 11 * 64; i += 256) sW1[i] = W1[i];
    for (int i = tid; i < 4096; i += 256) sW[i] = W2[i];   // W2 rows 0..63
    __syncthreads();

    // ---- stage 1: compute pf1 for point pt, channels cg*16 .. cg*16+15
    {
        int pt = tid >> 2;
        int cg = tid & 3;
        int gp = p0 + pt;

        float x  = pts[gp * 5 + 0];
        float y  = pts[gp * 5 + 1];
        float z  = pts[gp * 5 + 2];
        float p3 = pts[gp * 5 + 3];
        float p4 = pts[gp * 5 + 4];

        int flat = g_flat[gp];
        float inv = 1.0f / fmaxf((float)g_cnt[flat], 1.0f);
        float mx = g_vsum[3 * flat + 0] * inv;
        float my = g_vsum[3 * flat + 1] * inv;
        float mz = g_vsum[3 * flat + 2] * inv;

        int cxv = flat % NXY;
        int cyv = flat / NXY;

        float f[11];
        f[0] = x;  f[1] = y;  f[2] = z;  f[3] = p3;  f[4] = p4;
        f[5] = x - mx;  f[6] = y - my;  f[7] = z - mz;
        f[8]  = x - ((float)cxv * VXY + (VXY * 0.5f + PCMINX));
        f[9]  = y - ((float)cyv * VXY + (VXY * 0.5f + PCMINY));
        f[10] = z - (VZf * 0.5f + PCMINZ);

        const float4* w4 = (const float4*)sW1;   // [11][16] float4
        #pragma unroll
        for (int c4 = 0; c4 < 4; c4++) {
            int ch = cg * 16 + c4 * 4;           // channel base
            float a0 = 0.f, a1 = 0.f, a2 = 0.f, a3 = 0.f;
            #pragma unroll
            for (int k = 0; k < 11; k++) {
                float4 w = w4[k * 16 + (ch >> 2)];
                a0 = fmaf(f[k], w.x, a0);
                a1 = fmaf(f[k], w.y, a1);
                a2 = fmaf(f[k], w.z, a2);
                a3 = fmaf(f[k], w.w, a3);
            }
            a0 = fmaxf(a0, 0.f); a1 = fmaxf(a1, 0.f);
            a2 = fmaxf(a2, 0.f); a3 = fmaxf(a3, 0.f);

            float* d = sA + pt * SA_LD + ch;
            d[0] = a0; d[1] = a1; d[2] = a2; d[3] = a3;

            // relu >= 0, v1 zero-init -> int atomicMax exact
            int* vb = (int*)&g_v1[(size_t)flat * 64 + ch];
            if (a0 > 0.f) atomicMax(vb + 0, __float_as_int(a0));
            if (a1 > 0.f) atomicMax(vb + 1, __float_as_int(a1));
            if (a2 > 0.f) atomicMax(vb + 2, __float_as_int(a2));
            if (a3 > 0.f) atomicMax(vb + 3, __float_as_int(a3));
        }
    }
    __syncthreads();

    // ---- stage 2: GEMM s = sA @ sW  (4x4 micro-tile, K=64)
    float acc[4][4];
    #pragma unroll
    for (int r = 0; r < 4; r++)
        #pragma unroll
        for (int c = 0; c < 4; c++) acc[r][c] = 0.f;

    #pragma unroll 16
    for (int k = 0; k < 64; k++) {
        float4 b = *(const float4*)&sW[k * 64 + tx * 4];
        float a0 = sA[(ty * 4 + 0) * SA_LD + k];
        float a1 = sA[(ty * 4 + 1) * SA_LD + k];
        float a2 = sA[(ty * 4 + 2) * SA_LD + k];
        float a3 = sA[(ty * 4 + 3) * SA_LD + k];
        acc[0][0] = fmaf(a0, b.x, acc[0][0]); acc[0][1] = fmaf(a0, b.y, acc[0][1]);
        acc[0][2] = fmaf(a0, b.z, acc[0][2]); acc[0][3] = fmaf(a0, b.w, acc[0][3]);
        acc[1][0] = fmaf(a1, b.x, acc[1][0]); acc[1][1] = fmaf(a1, b.y, acc[1][1]);
        acc[1][2] = fmaf(a1, b.z, acc[1][2]); acc[1][3] = fmaf(a1, b.w, acc[1][3]);
        acc[2][0] = fmaf(a2, b.x, acc[2][0]); acc[2][1] = fmaf(a2, b.y, acc[2][1]);
        acc[2][2] = fmaf(a2, b.z, acc[2][2]); acc[2][3] = fmaf(a2, b.w, acc[2][3]);
        acc[3][0] = fmaf(a3, b.x, acc[3][0]); acc[3][1] = fmaf(a3, b.y, acc[3][1]);
        acc[3][2] = fmaf(a3, b.z, acc[3][2]); acc[3][3] = fmaf(a3, b.w, acc[3][3]);
    }

    // ---- epilogue: pre-relu scatter max into M
    #pragma unroll
    for (int r = 0; r < 4; r++) {
        int gp = p0 + ty * 4 + r;
        int fl = g_flat[gp];
        float* o = g_M + (size_t)fl * 64 + tx * 4;
        #pragma unroll
        for (int c = 0; c < 4; c++) atomicMaxFloat(o + c, acc[r][c]);
    }
}

// ---------------------------------------------------------------------------
// K3 (R11-proven): out[v] = relu(M[v] + v1[v] @ W2[64:]) dense per voxel.
// Empty voxels: M=-inf, v1=0 -> relu(-inf)=0 == where(occ,...,0).
// ---------------------------------------------------------------------------
__global__ __launch_bounds__(256)
void k_vox(const float* __restrict__ W2, float* __restrict__ out) {
    __shared__ __align__(16) float sW[64 * 64];
    __shared__ __align__(16) float sA[64 * SA_LD];

    int tid = threadIdx.x;
    int v0 = blockIdx.x * 64;
    int tx = tid & 15;
    int ty = tid >> 4;

    float acc[4][4];
    #pragma unroll
    for (int r = 0; r < 4; r++)
        #pragma unroll
        for (int c = 0; c < 4; c++) acc[r][c] = 0.f;

    for (int i = tid; i < 4096; i += 256) sW[i] = W2[4096 + i];  // rows 64..127
    {
        int r = tid >> 2, q = tid & 3;
        int v = min(v0 + r, CANVAS - 1);
        const float4* src = (const float4*)(g_v1 + (size_t)v * 64);
        #pragma unroll
        for (int i = 0; i < 4; i++) {
            float4 vv = src[q * 4 + i];
            *(float4*)&sA[r * SA_LD + (q * 4 + i) * 4] = vv;
        }
    }
    __syncthreads();

    #pragma unroll 16
    for (int k = 0; k < 64; k++) {
        float4 b = *(const float4*)&sW[k * 64 + tx * 4];
        float a0 = sA[(ty * 4 + 0) * SA_LD + k];
        float a1 = sA[(ty * 4 + 1) * SA_LD + k];
        float a2 = sA[(ty * 4 + 2) * SA_LD + k];
        float a3 = sA[(ty * 4 + 3) * SA_LD + k];
        acc[0][0] = fmaf(a0, b.x, acc[0][0]); acc[0][1] = fmaf(a0, b.y, acc[0][1]);
        acc[0][2] = fmaf(a0, b.z, acc[0][2]); acc[0][3] = fmaf(a0, b.w, acc[0][3]);
        acc[1][0] = fmaf(a1, b.x, acc[1][0]); acc[1][1] = fmaf(a1, b.y, acc[1][1]);
        acc[1][2] = fmaf(a1, b.z, acc[1][2]); acc[1][3] = fmaf(a1, b.w, acc[1][3]);
        acc[2][0] = fmaf(a2, b.x, acc[2][0]); acc[2][1] = fmaf(a2, b.y, acc[2][1]);
        acc[2][2] = fmaf(a2, b.z, acc[2][2]); acc[2][3] = fmaf(a2, b.w, acc[2][3]);
        acc[3][0] = fmaf(a3, b.x, acc[3][0]); acc[3][1] = fmaf(a3, b.y, acc[3][1]);
        acc[3][2] = fmaf(a3, b.z, acc[3][2]); acc[3][3] = fmaf(a3, b.w, acc[3][3]);
    }

    // epilogue: out = relu(acc + M), dense coalesced
    #pragma unroll
    for (int r = 0; r < 4; r++) {
        int v = v0 + ty * 4 + r;
        if (v >= CANVAS) continue;
        float4 m4 = *(const float4*)(g_M + (size_t)v * 64 + tx * 4);
        float4 o;
        o.x = fmaxf(acc[r][0] + m4.x, 0.f);
        o.y = fmaxf(acc[r][1] + m4.y, 0.f);
        o.z = fmaxf(acc[r][2] + m4.z, 0.f);
        o.w = fmaxf(acc[r][3] + m4.w, 0.f);
        *(float4*)(out + (size_t)v * 64 + tx * 4) = o;
    }
}

// ---------------------------------------------------------------------------
extern "C" void kernel_launch(void* const* d_in, const int* in_sizes, int n_in,
                              void* d_out, int out_size) {
    const float* points = (const float*)d_in[0];  // [400000, 5]
    const float* W1     = (const float*)d_in[1];  // [11, 64]
    const float* W2     = (const float*)d_in[2];  // [128, 64]
    float* out = (float*)d_out;                   // [219024, 64]

    // lazily created host-side objects (no device memory involved)
    static cudaStream_t s2 = nullptr;
    static cudaEvent_t  e_fork = nullptr, e_join = nullptr;
    if (s2 == nullptr) {
        cudaStreamCreateWithFlags(&s2, cudaStreamNonBlocking);
        cudaEventCreateWithFlags(&e_fork, cudaEventDisableTiming);
        cudaEventCreateWithFlags(&e_join, cudaEventDisableTiming);
    }

    // fork: big 112MB fill runs on s2 concurrently with init_small+scatter
    cudaEventRecord(e_fork, 0);
    cudaStreamWaitEvent(s2, e_fork, 0);
    k_init_big<<<8192, 256, 0, s2>>>();
    cudaEventRecord(e_join, s2);

    k_init_small<<<1024, 256>>>();
    k_scatter<<<(N_PTS + 255) / 256, 256>>>(points);

    // join: fused needs v1 zeros + M -inf
    cudaStreamWaitEvent(0, e_join, 0);

    k_fused<<<N_PTS / 64, 256>>>(points, W1, W2);
    k_vox<<<(CANVAS + 63) / 64, 256>>>(W2, out);
}